// round 13
// baseline (speedup 1.0000x reference)
#include <cuda_runtime.h>
#include <cuda_bf16.h>
#include <cstdint>

#define MARGIN 0.5f
#define POS_W 1.0f
#define NEG_W 1.0f

#define BLOCKS_PER_BATCH 4
#define R_THREADS 256
#define MAX_PARTIALS 8192
#define MAX_B 1024

// Scratch (allocations forbidden; __device__ global).
// Every slot used is rewritten each call -> no zeroing, no counters needed.
__device__ float g_partial[MAX_PARTIALS];

// ---- Kernel 1: pure stream reduce. No atomics, no fences, no tail. ----
__global__ __launch_bounds__(R_THREADS, 8) void stream_reduce_kernel(
    const float* __restrict__ graph, int ne_per_batch) {

    const int b = blockIdx.x / BLOCKS_PER_BATCH;
    const int chunk = blockIdx.x % BLOCKS_PER_BATCH;
    const int vec_per_batch = ne_per_batch >> 2;               // float4 count
    const int vec_per_chunk = vec_per_batch / BLOCKS_PER_BATCH;

    const float4* __restrict__ base =
        reinterpret_cast<const float4*>(graph) +
        (size_t)b * vec_per_batch + (size_t)chunk * vec_per_chunk;

    // 4 independent accumulators, unroll-4, plain LDG.128.
    float a0 = 0.0f, a1 = 0.0f, a2 = 0.0f, a3 = 0.0f;
    int i = threadIdx.x;
    const int stride = R_THREADS;
    const int n4 = vec_per_chunk & ~(4 * stride - 1);
    for (; i < n4; i += 4 * stride) {
        float4 v0 = base[i];
        float4 v1 = base[i + stride];
        float4 v2 = base[i + 2 * stride];
        float4 v3 = base[i + 3 * stride];
        a0 += (v0.x + v0.y) + (v0.z + v0.w);
        a1 += (v1.x + v1.y) + (v1.z + v1.w);
        a2 += (v2.x + v2.y) + (v2.z + v2.w);
        a3 += (v3.x + v3.y) + (v3.z + v3.w);
    }
    for (; i < vec_per_chunk; i += stride) {
        float4 v = base[i];
        a0 += (v.x + v.y) + (v.z + v.w);
    }
    float acc = (a0 + a1) + (a2 + a3);

    // block reduce
    #pragma unroll
    for (int off = 16; off > 0; off >>= 1)
        acc += __shfl_xor_sync(0xFFFFFFFFu, acc, off);

    __shared__ float warp_sums[R_THREADS / 32];
    const int lane = threadIdx.x & 31, wid = threadIdx.x >> 5;
    if (lane == 0) warp_sums[wid] = acc;
    __syncthreads();

    if (wid == 0) {
        float s = (lane < R_THREADS / 32) ? warp_sums[lane] : 0.0f;
        #pragma unroll
        for (int off = 4; off > 0; off >>= 1)
            s += __shfl_xor_sync(0xFFFFFFFFu, s, off);
        if (lane == 0) g_partial[blockIdx.x] = s;
    }
}

// ---- Kernel 2: one block. Full-matrix pair loss (symmetric trick). ----
// sum_{i<j} w = (sum_{i,j} w - sum_i w(i,i)) / 2; regular unrollable loop.
__global__ __launch_bounds__(R_THREADS) void pair_loss_kernel(
    const int* __restrict__ labels, float* __restrict__ out,
    int B, float inv_ne) {

    __shared__ float2 gl[MAX_B];   // .x = pooled sim, .y = label bits

    for (int t = threadIdx.x; t < B; t += R_THREADS) {
        float s = 0.0f;
        #pragma unroll
        for (int c = 0; c < BLOCKS_PER_BATCH; ++c)
            s += g_partial[t * BLOCKS_PER_BATCH + c];
        gl[t] = make_float2(s * inv_ne, __int_as_float(labels[t]));
    }
    __syncthreads();

    // Thread i handles full row i (all j), including j == i (subtracted below).
    float rowsum = 0.0f;
    float diag = 0.0f;
    if (threadIdx.x < B) {
        const float2 me = gl[threadIdx.x];
        const float gi = me.x;
        const int li = __float_as_int(me.y);

        float c0 = 0.f, c1 = 0.f, c2 = 0.f, c3 = 0.f;
        #pragma unroll 8
        for (int j = 0; j < B; ++j) {
            const float2 o = gl[j];
            const float sim = gi * o.x;
            const float pos = fmaxf(MARGIN - sim, 0.0f);
            const float neg = fmaxf(sim - (1.0f - MARGIN), 0.0f);
            const float w = (li == __float_as_int(o.y)) ? (POS_W * pos)
                                                        : (NEG_W * neg);
            switch (j & 3) {
                case 0: c0 += w; break;
                case 1: c1 += w; break;
                case 2: c2 += w; break;
                default: c3 += w; break;
            }
        }
        rowsum = (c0 + c1) + (c2 + c3);

        // diagonal term: same label with itself -> positive loss
        const float sim_d = gi * gi;
        diag = POS_W * fmaxf(MARGIN - sim_d, 0.0f);
    }

    float acc = rowsum - diag;   // 2x the upper-triangle contribution of row i

    #pragma unroll
    for (int off = 16; off > 0; off >>= 1)
        acc += __shfl_xor_sync(0xFFFFFFFFu, acc, off);

    const int lane = threadIdx.x & 31, wid = threadIdx.x >> 5;
    __shared__ float pw[R_THREADS / 32];
    if (lane == 0) pw[wid] = acc;
    __syncthreads();

    if (wid == 0) {
        float s = (lane < R_THREADS / 32) ? pw[lane] : 0.0f;
        #pragma unroll
        for (int off = 4; off > 0; off >>= 1)
            s += __shfl_xor_sync(0xFFFFFFFFu, s, off);
        if (lane == 0) {
            const float num_pairs = 0.5f * (float)B * (float)(B - 1);
            out[0] = (0.5f * s) / num_pairs;
        }
    }
}

extern "C" void kernel_launch(void* const* d_in, const int* in_sizes, int n_in,
                              void* d_out, int out_size) {
    const float* graph = (const float*)d_in[0];
    const int* labels = (const int*)d_in[1];
    float* out = (float*)d_out;

    const int total = in_sizes[0];   // B * N * N
    const int B = in_sizes[1];       // 256
    const int ne = total / B;        // N*N = 262144

    stream_reduce_kernel<<<B * BLOCKS_PER_BATCH, R_THREADS>>>(graph, ne);
    pair_loss_kernel<<<1, R_THREADS>>>(labels, out, B, 1.0f / (float)ne);
}

// round 14
// speedup vs baseline: 1.0927x; 1.0927x over previous
#include <cuda_runtime.h>
#include <cuda_bf16.h>
#include <cstdint>

#define MARGIN 0.5f
#define POS_W 1.0f
#define NEG_W 1.0f

#define BLOCKS_PER_BATCH 4
#define R_THREADS 256
#define MAX_PARTIALS 8192
#define MAX_B 1024

// Scratch (allocations forbidden; __device__ globals).
// Every g_partial slot used is rewritten each call -> no zeroing needed.
__device__ float g_partial[MAX_PARTIALS];
__device__ unsigned int g_arrival = 0;   // last block resets to 0 each call

__global__ __launch_bounds__(R_THREADS, 8) void fused_loss_kernel(
    const float* __restrict__ graph,
    const int* __restrict__ labels,
    float* __restrict__ out,
    int B, int ne_per_batch) {

    const int b = blockIdx.x / BLOCKS_PER_BATCH;
    const int chunk = blockIdx.x % BLOCKS_PER_BATCH;
    const int vec_per_batch = ne_per_batch >> 2;               // float4 count
    const int vec_per_chunk = vec_per_batch / BLOCKS_PER_BATCH;

    const float4* __restrict__ base =
        reinterpret_cast<const float4*>(graph) +
        (size_t)b * vec_per_batch + (size_t)chunk * vec_per_chunk;

    // Proven R4 stream loop: 4 independent accumulators, unroll-4, LDG.128.
    float a0 = 0.0f, a1 = 0.0f, a2 = 0.0f, a3 = 0.0f;
    int i = threadIdx.x;
    const int stride = R_THREADS;
    const int n4 = vec_per_chunk & ~(4 * stride - 1);
    for (; i < n4; i += 4 * stride) {
        float4 v0 = base[i];
        float4 v1 = base[i + stride];
        float4 v2 = base[i + 2 * stride];
        float4 v3 = base[i + 3 * stride];
        a0 += (v0.x + v0.y) + (v0.z + v0.w);
        a1 += (v1.x + v1.y) + (v1.z + v1.w);
        a2 += (v2.x + v2.y) + (v2.z + v2.w);
        a3 += (v3.x + v3.y) + (v3.z + v3.w);
    }
    for (; i < vec_per_chunk; i += stride) {
        float4 v = base[i];
        a0 += (v.x + v.y) + (v.z + v.w);
    }
    float acc = (a0 + a1) + (a2 + a3);

    // block reduce
    #pragma unroll
    for (int off = 16; off > 0; off >>= 1)
        acc += __shfl_xor_sync(0xFFFFFFFFu, acc, off);

    __shared__ float warp_sums[R_THREADS / 32];
    const int lane = threadIdx.x & 31, wid = threadIdx.x >> 5;
    if (lane == 0) warp_sums[wid] = acc;
    __syncthreads();

    __shared__ bool is_last;
    if (wid == 0) {
        float s = (lane < R_THREADS / 32) ? warp_sums[lane] : 0.0f;
        #pragma unroll
        for (int off = 4; off > 0; off >>= 1)
            s += __shfl_xor_sync(0xFFFFFFFFu, s, off);
        if (lane == 0) {
            g_partial[blockIdx.x] = s;
            __threadfence();
            unsigned int prev = atomicAdd(&g_arrival, 1u);
            is_last = (prev == gridDim.x - 1);
        }
    }
    __syncthreads();

    if (!is_last) return;

    // ---- tail (last block): full-matrix symmetric pair loss ----
    // sum_{i<j} w = (sum_{i,j} w - sum_i w(i,i)) / 2 ; uniform branch-free rows.
    if (threadIdx.x == 0) g_arrival = 0;   // reset for next graph replay

    __shared__ float2 gl[MAX_B];   // .x = pooled sim, .y = label bits
    const float inv_ne = 1.0f / (float)ne_per_batch;

    for (int t = threadIdx.x; t < B; t += R_THREADS) {
        float s = 0.0f;
        #pragma unroll
        for (int c = 0; c < BLOCKS_PER_BATCH; ++c)
            s += __ldcg(&g_partial[t * BLOCKS_PER_BATCH + c]);
        gl[t] = make_float2(s * inv_ne, __int_as_float(labels[t]));
    }
    __syncthreads();

    float row = 0.0f;
    if (threadIdx.x < B) {
        const float2 me = gl[threadIdx.x];
        const float gi = me.x;
        const int li = __float_as_int(me.y);

        float c0 = 0.f, c1 = 0.f, c2 = 0.f, c3 = 0.f;
        const int nb4 = B & ~3;
        for (int j = 0; j < nb4; j += 4) {
            const float2 o0 = gl[j];
            const float2 o1 = gl[j + 1];
            const float2 o2 = gl[j + 2];
            const float2 o3 = gl[j + 3];
            const float s0 = gi * o0.x, s1 = gi * o1.x;
            const float s2 = gi * o2.x, s3 = gi * o3.x;
            const float w0 = (li == __float_as_int(o0.y))
                ? POS_W * fmaxf(MARGIN - s0, 0.0f)
                : NEG_W * fmaxf(s0 - (1.0f - MARGIN), 0.0f);
            const float w1 = (li == __float_as_int(o1.y))
                ? POS_W * fmaxf(MARGIN - s1, 0.0f)
                : NEG_W * fmaxf(s1 - (1.0f - MARGIN), 0.0f);
            const float w2 = (li == __float_as_int(o2.y))
                ? POS_W * fmaxf(MARGIN - s2, 0.0f)
                : NEG_W * fmaxf(s2 - (1.0f - MARGIN), 0.0f);
            const float w3 = (li == __float_as_int(o3.y))
                ? POS_W * fmaxf(MARGIN - s3, 0.0f)
                : NEG_W * fmaxf(s3 - (1.0f - MARGIN), 0.0f);
            c0 += w0; c1 += w1; c2 += w2; c3 += w3;
        }
        for (int j = nb4; j < B; ++j) {
            const float2 o = gl[j];
            const float s = gi * o.x;
            c0 += (li == __float_as_int(o.y))
                ? POS_W * fmaxf(MARGIN - s, 0.0f)
                : NEG_W * fmaxf(s - (1.0f - MARGIN), 0.0f);
        }
        // subtract diagonal (j == i, same label with itself -> pos loss)
        const float wd = POS_W * fmaxf(MARGIN - gi * gi, 0.0f);
        row = ((c0 + c1) + (c2 + c3)) - wd;
    }

    #pragma unroll
    for (int off = 16; off > 0; off >>= 1)
        row += __shfl_xor_sync(0xFFFFFFFFu, row, off);

    __shared__ float pw[R_THREADS / 32];
    if (lane == 0) pw[wid] = row;
    __syncthreads();

    if (wid == 0) {
        float s = (lane < R_THREADS / 32) ? pw[lane] : 0.0f;
        #pragma unroll
        for (int off = 4; off > 0; off >>= 1)
            s += __shfl_xor_sync(0xFFFFFFFFu, s, off);
        if (lane == 0) {
            const float num_pairs = 0.5f * (float)B * (float)(B - 1);
            out[0] = (0.5f * s) / num_pairs;
        }
    }
}

extern "C" void kernel_launch(void* const* d_in, const int* in_sizes, int n_in,
                              void* d_out, int out_size) {
    const float* graph = (const float*)d_in[0];
    const int* labels = (const int*)d_in[1];
    float* out = (float*)d_out;

    const int total = in_sizes[0];   // B * N * N
    const int B = in_sizes[1];       // 256
    const int ne = total / B;        // N*N = 262144

    fused_loss_kernel<<<B * BLOCKS_PER_BATCH, R_THREADS>>>(graph, labels, out, B, ne);
}

// round 15
// speedup vs baseline: 1.1341x; 1.0379x over previous
#include <cuda_runtime.h>
#include <cuda_bf16.h>
#include <cstdint>

#define MARGIN 0.5f
#define POS_W 1.0f
#define NEG_W 1.0f

#define BLOCKS_PER_BATCH 4
#define R_THREADS 256
#define MAX_PARTIALS 8192
#define MAX_B 1024

// Scratch (allocations forbidden; __device__ globals).
// Every g_partial slot used is rewritten each call -> no zeroing needed.
__device__ float g_partial[MAX_PARTIALS];
__device__ unsigned int g_arrival = 0;   // last block resets to 0 each call

// Release-ordered arrival: orders this block's prior global stores to L2
// WITHOUT the L1D-flushing CCTL.IVALL that __threadfence() emits.
__device__ __forceinline__ unsigned int arrive_release(unsigned int* ctr) {
    unsigned int prev;
    asm volatile("atom.release.gpu.global.add.u32 %0, [%1], %2;"
                 : "=r"(prev) : "l"(ctr), "r"(1u) : "memory");
    return prev;
}

__global__ __launch_bounds__(R_THREADS, 8) void fused_loss_kernel(
    const float* __restrict__ graph,
    const int* __restrict__ labels,
    float* __restrict__ out,
    int B, int ne_per_batch) {

    const int b = blockIdx.x / BLOCKS_PER_BATCH;
    const int chunk = blockIdx.x % BLOCKS_PER_BATCH;
    const int vec_per_batch = ne_per_batch >> 2;               // float4 count
    const int vec_per_chunk = vec_per_batch / BLOCKS_PER_BATCH;

    const float4* __restrict__ base =
        reinterpret_cast<const float4*>(graph) +
        (size_t)b * vec_per_batch + (size_t)chunk * vec_per_chunk;

    // Proven R4 stream loop: 4 independent accumulators, unroll-4, LDG.128.
    float a0 = 0.0f, a1 = 0.0f, a2 = 0.0f, a3 = 0.0f;
    int i = threadIdx.x;
    const int stride = R_THREADS;
    const int n4 = vec_per_chunk & ~(4 * stride - 1);
    for (; i < n4; i += 4 * stride) {
        float4 v0 = base[i];
        float4 v1 = base[i + stride];
        float4 v2 = base[i + 2 * stride];
        float4 v3 = base[i + 3 * stride];
        a0 += (v0.x + v0.y) + (v0.z + v0.w);
        a1 += (v1.x + v1.y) + (v1.z + v1.w);
        a2 += (v2.x + v2.y) + (v2.z + v2.w);
        a3 += (v3.x + v3.y) + (v3.z + v3.w);
    }
    for (; i < vec_per_chunk; i += stride) {
        float4 v = base[i];
        a0 += (v.x + v.y) + (v.z + v.w);
    }
    float acc = (a0 + a1) + (a2 + a3);

    // block reduce
    #pragma unroll
    for (int off = 16; off > 0; off >>= 1)
        acc += __shfl_xor_sync(0xFFFFFFFFu, acc, off);

    __shared__ float warp_sums[R_THREADS / 32];
    const int lane = threadIdx.x & 31, wid = threadIdx.x >> 5;
    if (lane == 0) warp_sums[wid] = acc;
    __syncthreads();

    __shared__ bool is_last;
    if (wid == 0) {
        float s = (lane < R_THREADS / 32) ? warp_sums[lane] : 0.0f;
        #pragma unroll
        for (int off = 4; off > 0; off >>= 1)
            s += __shfl_xor_sync(0xFFFFFFFFu, s, off);
        if (lane == 0) {
            // Bypass L1 on the partial store so the release-ordered arrival
            // publishes it at L2 (point of coherence) with no fence.
            __stcg(&g_partial[blockIdx.x], s);
            unsigned int prev = arrive_release(&g_arrival);
            is_last = (prev == gridDim.x - 1);
        }
    }
    __syncthreads();

    if (!is_last) return;

    // ---- tail (last block): full-matrix symmetric pair loss ----
    // sum_{i<j} w = (sum_{i,j} w - sum_i w(i,i)) / 2 ; uniform branch-free rows.
    if (threadIdx.x == 0) g_arrival = 0;   // reset for next graph replay

    __shared__ float2 gl[MAX_B];   // .x = pooled sim, .y = label bits
    const float inv_ne = 1.0f / (float)ne_per_batch;

    for (int t = threadIdx.x; t < B; t += R_THREADS) {
        float s = 0.0f;
        #pragma unroll
        for (int c = 0; c < BLOCKS_PER_BATCH; ++c)
            s += __ldcg(&g_partial[t * BLOCKS_PER_BATCH + c]);
        gl[t] = make_float2(s * inv_ne, __int_as_float(labels[t]));
    }
    __syncthreads();

    float row = 0.0f;
    if (threadIdx.x < B) {
        const float2 me = gl[threadIdx.x];
        const float gi = me.x;
        const int li = __float_as_int(me.y);

        float c0 = 0.f, c1 = 0.f, c2 = 0.f, c3 = 0.f;
        const int nb4 = B & ~3;
        for (int j = 0; j < nb4; j += 4) {
            const float2 o0 = gl[j];
            const float2 o1 = gl[j + 1];
            const float2 o2 = gl[j + 2];
            const float2 o3 = gl[j + 3];
            const float s0 = gi * o0.x, s1 = gi * o1.x;
            const float s2 = gi * o2.x, s3 = gi * o3.x;
            const float w0 = (li == __float_as_int(o0.y))
                ? POS_W * fmaxf(MARGIN - s0, 0.0f)
                : NEG_W * fmaxf(s0 - (1.0f - MARGIN), 0.0f);
            const float w1 = (li == __float_as_int(o1.y))
                ? POS_W * fmaxf(MARGIN - s1, 0.0f)
                : NEG_W * fmaxf(s1 - (1.0f - MARGIN), 0.0f);
            const float w2 = (li == __float_as_int(o2.y))
                ? POS_W * fmaxf(MARGIN - s2, 0.0f)
                : NEG_W * fmaxf(s2 - (1.0f - MARGIN), 0.0f);
            const float w3 = (li == __float_as_int(o3.y))
                ? POS_W * fmaxf(MARGIN - s3, 0.0f)
                : NEG_W * fmaxf(s3 - (1.0f - MARGIN), 0.0f);
            c0 += w0; c1 += w1; c2 += w2; c3 += w3;
        }
        for (int j = nb4; j < B; ++j) {
            const float2 o = gl[j];
            const float s = gi * o.x;
            c0 += (li == __float_as_int(o.y))
                ? POS_W * fmaxf(MARGIN - s, 0.0f)
                : NEG_W * fmaxf(s - (1.0f - MARGIN), 0.0f);
        }
        // subtract diagonal (j == i, same label with itself -> pos loss)
        const float wd = POS_W * fmaxf(MARGIN - gi * gi, 0.0f);
        row = ((c0 + c1) + (c2 + c3)) - wd;
    }

    #pragma unroll
    for (int off = 16; off > 0; off >>= 1)
        row += __shfl_xor_sync(0xFFFFFFFFu, row, off);

    __shared__ float pw[R_THREADS / 32];
    if (lane == 0) pw[wid] = row;
    __syncthreads();

    if (wid == 0) {
        float s = (lane < R_THREADS / 32) ? pw[lane] : 0.0f;
        #pragma unroll
        for (int off = 4; off > 0; off >>= 1)
            s += __shfl_xor_sync(0xFFFFFFFFu, s, off);
        if (lane == 0) {
            const float num_pairs = 0.5f * (float)B * (float)(B - 1);
            out[0] = (0.5f * s) / num_pairs;
        }
    }
}

extern "C" void kernel_launch(void* const* d_in, const int* in_sizes, int n_in,
                              void* d_out, int out_size) {
    const float* graph = (const float*)d_in[0];
    const int* labels = (const int*)d_in[1];
    float* out = (float*)d_out;

    const int total = in_sizes[0];   // B * N * N
    const int B = in_sizes[1];       // 256
    const int ne = total / B;        // N*N = 262144

    fused_loss_kernel<<<B * BLOCKS_PER_BATCH, R_THREADS>>>(graph, labels, out, B, ne);
}